// round 16
// baseline (speedup 1.0000x reference)
#include <cuda_runtime.h>
#include <cuda_bf16.h>
#include <math.h>

#define BB 16
#define TT 1024
#define VV 4096
#define PP 100
#define LL 128
#define NEDIT 64          // 4 blocks per b, 32 paths per block (4 lanes/path)
#define NSCORE 200        // fat scores blocks: 8 bp each (compact + gather)

// scratch (allocation-free rule: __device__ globals; all zero-init at load)
__device__ unsigned g_map[BB * VV];      // per-b vocab -> (128-minpos), 0=absent
__device__ unsigned char g_ctok[BB * PP * TT + 128];   // compacted ids (u8)
__device__ int g_clen[BB * PP];
__device__ unsigned g_cflag[BB * PP];    // per-bp compaction-done flag
__device__ int g_peqdone[BB];            // edit PEQ-build counter per b
__device__ float g_scores[BB * PP];
__device__ float g_wers[BB * PP];
__device__ unsigned g_done;

#define LOP3_(r, a, b, c, imm)                                          \
    asm("lop3.b32 %0, %1, %2, %3, %4;"                                  \
        : "=r"(r) : "r"(a), "r"(b), "r"(c), "n"(imm))

// ---------------------------------------------------------------------------
// Kernel A: per-b map scatter + per-call aux reset.
// map[b][c] = 128 - minpos(c) via atomicMax over zeroed map (0 = absent).
// Map zero-state is restored by the PREVIOUS call's edit blocks (exact same
// label entries), so no full clear is ever needed.
// ---------------------------------------------------------------------------
__global__ void __launch_bounds__(128) scatter_kernel(
    const int* __restrict__ labels,
    const int* __restrict__ llen)
{
    const int b = blockIdx.x, tid = threadIdx.x;
    if (tid < PP) g_cflag[b * PP + tid] = 0u;
    if (tid == 0) g_peqdone[b] = 0;
    if (b == 0 && tid == 0) g_done = 0;
    if (tid < llen[b])
        atomicMax(&g_map[(size_t)b * VV + labels[b * LL + tid]],
                  128u - (unsigned)tid);
}

// ---------------------------------------------------------------------------
// Compaction of one (b,p): CTC-collapse + remap to u8 ids.
// valid = tok!=0 && tok!=raw_prev && t<len.  id = map[c]?129-map[c]:0.
// Runs inside scores blocks (128 threads).
// ---------------------------------------------------------------------------
__device__ __forceinline__ void compact_one(
    int bp, const int* __restrict__ paths, int len)
{
    const int b  = bp / PP;
    const int* pp = paths + (size_t)bp * TT;
    const unsigned* map = g_map + (size_t)b * VV;
    const int tid = threadIdx.x;
    const int t0 = tid * 8;

    int4 A = *(const int4*)(pp + t0);
    int4 Bv = *(const int4*)(pp + t0 + 4);
    int tok[8] = {A.x, A.y, A.z, A.w, Bv.x, Bv.y, Bv.z, Bv.w};
    const int prev0 = (t0 == 0) ? -1 : __ldg(pp + t0 - 1);

    unsigned char id[8];
    #pragma unroll
    for (int i = 0; i < 8; ++i) {
        unsigned val = __ldg(map + tok[i]);
        id[i] = val ? (unsigned char)(129u - val) : (unsigned char)0;
    }

    unsigned flags = 0;
    int cnt = 0;
    #pragma unroll
    for (int i = 0; i < 8; ++i) {
        int pr = (i == 0) ? prev0 : tok[i - 1];
        int v = ((t0 + i) < len) & (tok[i] != 0) & (tok[i] != pr);
        flags |= (unsigned)v << i;
        cnt += v;
    }

    const int lane = tid & 31, w = tid >> 5;
    int inc = cnt;
    #pragma unroll
    for (int o = 1; o < 32; o <<= 1) {
        int nn = __shfl_up_sync(0xffffffffu, inc, o);
        if (lane >= o) inc += nn;
    }
    __shared__ int wtot[4];
    if (lane == 31) wtot[w] = inc;
    __syncthreads();
    int wbase = 0;
    #pragma unroll
    for (int i = 0; i < 4; ++i) wbase += (i < w) ? wtot[i] : 0;
    int base = wbase + inc - cnt;

    unsigned char* out = g_ctok + (size_t)bp * TT;
    #pragma unroll
    for (int i = 0; i < 8; ++i)
        if ((flags >> i) & 1u) out[base++] = id[i];

    __threadfence();                       // publish this thread's ctok stores
    __syncthreads();
    if (tid == 0) {
        g_clen[bp] = wtot[0] + wtot[1] + wtot[2] + wtot[3];
        __threadfence();
        atomicExch(&g_cflag[bp], 1u);      // release flag
    }
    __syncthreads();
}

// ---------------------------------------------------------------------------
// Skew-2 Myers step block: lane w owns word w, token t = J + i - 2w.
// Message (carry/hp31/hn31) produced by lane w-1 two wall-steps earlier ->
// shfl issues against already-final m2: SHFL is OFF the dependency chain.
// Score via final-state invariant (no per-step tracking).
// ---------------------------------------------------------------------------
template<bool GUARD>
__device__ __forceinline__ void block16_sk2(
    const unsigned* __restrict__ peqw, int w, int base_t, int n,
    unsigned C0, unsigned C1, unsigned C2, unsigned C3, unsigned Cn0,
    unsigned& VP, unsigned& VN, unsigned& Eq_a, unsigned& Eq_b,
    unsigned& m1, unsigned& m2, unsigned c_and, unsigned hp_pat)
{
    unsigned Cw[4] = {C0, C1, C2, C3};
    #pragma unroll
    for (int i = 0; i < 16; ++i) {
        const unsigned msgIn = __shfl_up_sync(0xffffffffu, m2, 1, 4);
        m2 = m1;

        const unsigned Eq = (i & 1) ? Eq_b : Eq_a;
        const int k = i + 2;                     // depth-2 PEQ prefetch
        const unsigned idn = (k < 16)
            ? __byte_perm(Cw[k >> 2], 0, 0x4440 | (k & 3))
            : __byte_perm(Cn0, 0, 0x4440 | (k & 3));
        const unsigned Eqn = peqw[(idn << 2) + w];
        if (i & 1) Eq_b = Eqn; else Eq_a = Eqn;

        const unsigned mAA  = (msgIn & c_and) | hp_pat;
        const unsigned cin  = mAA & 1u;
        const unsigned hpin = (mAA >> 1) & 1u;
        const unsigned hnin = (mAA >> 2) & 1u;

        const unsigned a = Eq & VP;
        const unsigned long long wide = (unsigned long long)a + VP + cin;
        const unsigned sum  = (unsigned)wide;
        const unsigned cout = (unsigned)(wide >> 32);
        unsigned X; LOP3_(X, sum, VP, Eq, 0xBE);     // (sum^VP)|Eq
        const unsigned D = X | VN;
        unsigned HP; LOP3_(HP, VN, D, VP, 0xF1);     // VN | ~(D|VP)
        const unsigned HN = VP & D;

        m1 = cout | (((HP >> 31) & 1u) << 1) | ((HN >> 31) << 2);

        const unsigned HPs = (HP << 1) | hpin;
        const unsigned HNs = (HN << 1) | hnin;
        unsigned nVP; LOP3_(nVP, HNs, D, HPs, 0xF1);
        const unsigned nVN = D & HPs;
        if (GUARD) {
            const bool act = ((unsigned)(base_t + i) < (unsigned)n);
            VP = act ? nVP : VP;
            VN = act ? nVN : VN;
        } else { VP = nVP; VN = nVN; }
    }
}

// window of 16 bytes starting at byte (J - 2w), built from P (J-16..) / B (J..)
__device__ __forceinline__ void win2(
    int w, uint4 P, uint4 B,
    unsigned& C0, unsigned& C1, unsigned& C2, unsigned& C3)
{
    if (w == 0)      { C0 = B.x; C1 = B.y; C2 = B.z; C3 = B.w; }
    else if (w == 1) { C0 = __funnelshift_r(P.w, B.x, 16);
                       C1 = __funnelshift_r(B.x, B.y, 16);
                       C2 = __funnelshift_r(B.y, B.z, 16);
                       C3 = __funnelshift_r(B.z, B.w, 16); }
    else if (w == 2) { C0 = P.w; C1 = B.x; C2 = B.y; C3 = B.z; }
    else             { C0 = __funnelshift_r(P.z, P.w, 16);
                       C1 = __funnelshift_r(P.w, B.x, 16);
                       C2 = __funnelshift_r(B.x, B.y, 16);
                       C3 = __funnelshift_r(B.y, B.z, 16); }
}
__device__ __forceinline__ unsigned win2_first(int w, uint4 B, uint4 Bn)
{
    if (w == 0)      return Bn.x;
    else if (w == 1) return __funnelshift_r(B.w, Bn.x, 16);
    else if (w == 2) return B.w;
    else             return __funnelshift_r(B.z, B.w, 16);
}

__device__ __forceinline__ void edit_body(
    int blk, const int* __restrict__ labels, const int* __restrict__ llen,
    char* smem_raw)
{
    unsigned* peqw = (unsigned*)smem_raw;    // 256 ids * 4 words = 4KB
    const int b = blk >> 2;
    const int pbase = (blk & 3) * 32;
    const int tid = threadIdx.x;

    for (int i = tid; i < 1024; i += 128) peqw[i] = 0u;
    __syncthreads();
    const int m = llen[b];                   // 64..128, uniform per b
    if (tid < m) {
        int c = labels[b * LL + tid];
        unsigned val = __ldg(&g_map[(size_t)b * VV + c]);   // >=1 here
        atomicOr(&peqw[((129u - val) << 2) + (tid >> 5)], 1u << (tid & 31));
    }
    __syncthreads();
    if (tid == 0) atomicAdd(&g_peqdone[b], 1);   // done reading g_map

    // wait for our 32 paths' compaction flags
    const int p_raw = pbase + (tid >> 2);
    if (tid < 32) {
        const int fidx = b * PP + min(pbase + tid, PP - 1);
        while (atomicAdd(&g_cflag[fidx], 0u) == 0u) {}
        __threadfence();
    }
    __syncthreads();

    const int w = tid & 3;
    const int p = (p_raw < PP) ? p_raw : (PP - 1);
    const int gp = b * PP + p;
    const int n = g_clen[gp];
    const unsigned char* ct = g_ctok + (size_t)gp * TT;

    int nMax = n, nMin = n;
    #pragma unroll
    for (int o = 16; o; o >>= 1) {
        nMax = max(nMax, __shfl_xor_sync(0xffffffffu, nMax, o));
        nMin = min(nMin, __shfl_xor_sync(0xffffffffu, nMin, o));
    }
    const int nWall = ((nMax + 6) + 15) & ~15;

    unsigned mask;
    if (w < 2)       mask = ~0u;
    else if (w == 2) mask = (m >= 96)  ? ~0u : ((m > 64) ? ((1u << (m - 64)) - 1u) : 0u);
    else             mask = (m >= 128) ? ~0u : ((m > 96) ? ((1u << (m - 96)) - 1u) : 0u);
    unsigned VP = mask, VN = 0u;

    const unsigned c_and  = w ? 7u : 0u;
    const unsigned hp_pat = w ? 0u : 2u;     // lane0: hpin=1 (D[j][0]=j boundary)
    unsigned m1 = 0u, m2 = 0u;

    uint4 P  = make_uint4(0, 0, 0, 0);
    uint4 B  = *(const uint4*)(ct);
    uint4 Bn = *(const uint4*)(ct + 16);
    unsigned C0, C1, C2, C3;
    win2(w, P, B, C0, C1, C2, C3);
    unsigned Eq_a = peqw[(__byte_perm(C0, 0, 0x4440) << 2) + w];
    unsigned Eq_b = peqw[(__byte_perm(C0, 0, 0x4441) << 2) + w];

    for (int J = 0; J < nWall; J += 16) {
        const uint4 Bf = *(const uint4*)(ct + J + 32);   // within +128 pad
        const unsigned Cn0 = win2_first(w, B, Bn);
        const int base_t = J - 2 * w;
        if (J == 0 || (J + 15) >= nMin)
            block16_sk2<true >(peqw, w, base_t, n, C0, C1, C2, C3, Cn0,
                               VP, VN, Eq_a, Eq_b, m1, m2, c_and, hp_pat);
        else
            block16_sk2<false>(peqw, w, base_t, n, C0, C1, C2, C3, Cn0,
                               VP, VN, Eq_a, Eq_b, m1, m2, c_and, hp_pat);
        P = B; B = Bn; Bn = Bf;
        win2(w, P, B, C0, C1, C2, C3);
    }

    // D[n][m] = n + popc(VP&mask) - popc(VN&mask) summed over the 4 words
    int partial = __popc(VP & mask) - __popc(VN & mask);
    partial += __shfl_xor_sync(0xffffffffu, partial, 1, 4);
    partial += __shfl_xor_sync(0xffffffffu, partial, 2, 4);
    if ((tid & 3) == 0 && p_raw < PP)
        g_wers[b * PP + p_raw] = (float)(n + partial);
    __syncthreads();

    // group 0 restores g_map[b] to zero-state for the next call, once no
    // reader remains: all 100 compactions flagged + all 4 PEQ builds done.
    if ((blk & 3) == 0) {
        if (tid < PP) { while (atomicAdd(&g_cflag[b * PP + tid], 0u) == 0u) {} }
        if (tid == 0) { while (atomicAdd(&g_peqdone[b], 0) < 4) {} }
        __syncthreads();
        if (tid < m) g_map[(size_t)b * VV + labels[b * LL + tid]] = 0u;
    }
    __syncthreads();
}

// ---------------------------------------------------------------------------
// Scores blocks: compact 8 bp (sets flags -> unblocks edit), then gather.
// log-softmax normalizer cancels in the per-b softmax over paths.
// ---------------------------------------------------------------------------
__device__ __forceinline__ void scores_multi(
    int blk, const float* __restrict__ em, const int* __restrict__ elen,
    const int* __restrict__ paths, char* smem_raw)
{
    const int tid = threadIdx.x;
    const int t0 = tid * 8;
    float* ws = (float*)smem_raw;

    #pragma unroll 1
    for (int q = 0; q < 8; ++q) {
        const int bp = blk * 8 + q;
        compact_one(bp, paths, elen[bp / PP]);
    }

    #pragma unroll 1
    for (int q = 0; q < 8; ++q) {
        const int bp  = blk * 8 + q;
        const int b   = bp / PP;
        const int len = elen[b];
        const int* pp = paths + (size_t)bp * TT;
        const float* eb = em + (size_t)b * TT * VV;

        int4 A = *(const int4*)(pp + t0);
        int4 Bv = *(const int4*)(pp + t0 + 4);
        int tok[8] = {A.x, A.y, A.z, A.w, Bv.x, Bv.y, Bv.z, Bv.w};

        float a0 = 0.f, a1 = 0.f, a2 = 0.f, a3 = 0.f;
        #pragma unroll
        for (int i = 0; i < 8; i += 4) {
            if (t0 + i + 0 < len) a0 += __ldg(eb + (size_t)(t0 + i + 0) * VV + tok[i + 0]);
            if (t0 + i + 1 < len) a1 += __ldg(eb + (size_t)(t0 + i + 1) * VV + tok[i + 1]);
            if (t0 + i + 2 < len) a2 += __ldg(eb + (size_t)(t0 + i + 2) * VV + tok[i + 2]);
            if (t0 + i + 3 < len) a3 += __ldg(eb + (size_t)(t0 + i + 3) * VV + tok[i + 3]);
        }
        float acc = (a0 + a1) + (a2 + a3);
        #pragma unroll
        for (int o = 16; o; o >>= 1) acc += __shfl_down_sync(0xffffffffu, acc, o);
        if ((tid & 31) == 0) ws[tid >> 5] = acc;
        __syncthreads();
        if (tid == 0) g_scores[bp] = ws[0] + ws[1] + ws[2] + ws[3];
        __syncthreads();
    }
}

__device__ __forceinline__ void finalize_body(float* out, char* smem_raw)
{
    float* red = (float*)smem_raw;
    const int tid = threadIdx.x;
    float total = 0.f;
    __threadfence();

    for (int b = 0; b < BB; ++b) {
        float s = (tid < PP) ? g_scores[b * PP + tid] : -3.0e38f;
        red[tid] = s; __syncthreads();
        #pragma unroll
        for (int o = 64; o; o >>= 1) {
            if (tid < o) red[tid] = fmaxf(red[tid], red[tid + o]);
            __syncthreads();
        }
        const float mx = red[0];
        __syncthreads();

        const float e  = (tid < PP) ? expf(s - mx) : 0.f;
        const float ew = (tid < PP) ? e * g_wers[b * PP + tid] : 0.f;

        red[tid] = e; __syncthreads();
        #pragma unroll
        for (int o = 64; o; o >>= 1) {
            if (tid < o) red[tid] += red[tid + o];
            __syncthreads();
        }
        const float Z = red[0];
        __syncthreads();

        red[tid] = ew; __syncthreads();
        #pragma unroll
        for (int o = 64; o; o >>= 1) {
            if (tid < o) red[tid] += red[tid + o];
            __syncthreads();
        }
        const float S = red[0];
        __syncthreads();

        total += S / Z;
    }
    if (tid == 0) out[0] = total;
}

__global__ void __launch_bounds__(128) fused_kernel(
    const float* __restrict__ em,
    const int* __restrict__ elen,
    const int* __restrict__ paths,
    const int* __restrict__ labels,
    const int* __restrict__ llen,
    float* __restrict__ out)
{
    extern __shared__ char smem_raw[];
    __shared__ unsigned s_rank;

    if (blockIdx.x < NEDIT)
        edit_body(blockIdx.x, labels, llen, smem_raw);
    else
        scores_multi(blockIdx.x - NEDIT, em, elen, paths, smem_raw);

    if (threadIdx.x == 0) {
        __threadfence();
        s_rank = atomicAdd(&g_done, 1u);
    }
    __syncthreads();
    if (s_rank == (unsigned)(NEDIT + NSCORE - 1))
        finalize_body(out, smem_raw);
}

// ---------------------------------------------------------------------------
extern "C" void kernel_launch(void* const* d_in, const int* in_sizes, int n_in,
                              void* d_out, int out_size)
{
    const float* em     = (const float*)d_in[0];  // (B,T,V) f32
    const int*   elen   = (const int*)  d_in[1];  // (B,)
    const int*   labels = (const int*)  d_in[2];  // (B,L)
    const int*   llen   = (const int*)  d_in[3];  // (B,)
    const int*   paths  = (const int*)  d_in[4];  // (B,P,T)

    scatter_kernel<<<BB, 128>>>(labels, llen);

    const int smem = 4096 + 512;   // peq (4KB) + reduction scratch
    fused_kernel<<<NEDIT + NSCORE, 128, smem>>>(em, elen, paths, labels, llen,
                                                (float*)d_out);
}

// round 17
// speedup vs baseline: 1.1667x; 1.1667x over previous
#include <cuda_runtime.h>
#include <cuda_bf16.h>
#include <math.h>

#define BB 16
#define TT 1024
#define VV 4096
#define PP 100
#define LL 128
#define NEDIT 64          // 4 blocks per b, 32 paths per block (4 lanes/path)
#define NSCORE 200        // fat scores blocks, 8 bp each

// scratch (allocation-free rule: __device__ globals)
__device__ unsigned g_map[BB * VV];                       // per-b vocab -> minpos
__device__ unsigned char g_ctok[BB * PP * TT + 128];      // compacted token ids (u8)
__device__ int g_clen[BB * PP];
__device__ float g_scores[BB * PP];
__device__ float g_wers[BB * PP];
__device__ unsigned g_done;

// forced 3-input LOP3 with explicit immLut
#define LOP3_(r, a, b, c, imm)                                          \
    asm("lop3.b32 %0, %1, %2, %3, %4;"                                  \
        : "=r"(r) : "r"(a), "r"(b), "r"(c), "n"(imm))

// ---------------------------------------------------------------------------
// Kernel A1: wide clear of the vocab map (+ done counter).
// ---------------------------------------------------------------------------
__global__ void __launch_bounds__(128) clear_kernel()
{
    const unsigned idx = blockIdx.x * 128u + threadIdx.x;
    uint4* mp = (uint4*)g_map;
    const uint4 f = make_uint4(~0u, ~0u, ~0u, ~0u);
    for (unsigned i = idx; i < (BB * VV) / 4; i += gridDim.x * 128u) mp[i] = f;
    if (idx == 0) g_done = 0;
}

// ---------------------------------------------------------------------------
// Kernel A2: map[b][c] = min label position of char c. id(c) = map[c]+1
// (wraps to 0 for chars not in the label).
// ---------------------------------------------------------------------------
__global__ void __launch_bounds__(128) scatter_kernel(
    const int* __restrict__ labels,
    const int* __restrict__ llen)
{
    const int b = blockIdx.x, tid = threadIdx.x;
    if (tid < llen[b])
        atomicMin(&g_map[(size_t)b * VV + labels[b * LL + tid]], (unsigned)tid);
}

// ---------------------------------------------------------------------------
// Kernel B: CTC-collapse + remap to u8 ids. One block per (b,p).
// valid = tok!=0 && tok!=raw_prev && t<len.
// ---------------------------------------------------------------------------
__global__ void __launch_bounds__(128) compact_kernel(
    const int* __restrict__ paths,
    const int* __restrict__ elen)
{
    const int bp = blockIdx.x;
    const int b  = bp / PP;
    const int len = elen[b];
    const int* pp = paths + (size_t)bp * TT;
    const unsigned* map = g_map + (size_t)b * VV;
    const int tid = threadIdx.x;
    const int t0 = tid * 8;

    int4 A = *(const int4*)(pp + t0);
    int4 Bv = *(const int4*)(pp + t0 + 4);
    int tok[8] = {A.x, A.y, A.z, A.w, Bv.x, Bv.y, Bv.z, Bv.w};
    const int prev0 = (t0 == 0) ? -1 : __ldg(pp + t0 - 1);

    unsigned char id[8];
    #pragma unroll
    for (int i = 0; i < 8; ++i)
        id[i] = (unsigned char)(__ldg(map + tok[i]) + 1u);   // 0 if not in label

    unsigned flags = 0;
    int cnt = 0;
    #pragma unroll
    for (int i = 0; i < 8; ++i) {
        int pr = (i == 0) ? prev0 : tok[i - 1];
        int v = ((t0 + i) < len) & (tok[i] != 0) & (tok[i] != pr);
        flags |= (unsigned)v << i;
        cnt += v;
    }

    const int lane = tid & 31, w = tid >> 5;
    int inc = cnt;
    #pragma unroll
    for (int o = 1; o < 32; o <<= 1) {
        int nn = __shfl_up_sync(0xffffffffu, inc, o);
        if (lane >= o) inc += nn;
    }
    __shared__ int wtot[4];
    if (lane == 31) wtot[w] = inc;
    __syncthreads();
    int wbase = 0;
    #pragma unroll
    for (int i = 0; i < 4; ++i) wbase += (i < w) ? wtot[i] : 0;
    int base = wbase + inc - cnt;

    unsigned char* out = g_ctok + (size_t)bp * TT;
    #pragma unroll
    for (int i = 0; i < 8; ++i)
        if ((flags >> i) & 1u) out[base++] = id[i];
    __syncthreads();
    if (tid == 0) g_clen[bp] = wtot[0] + wtot[1] + wtot[2] + wtot[3];
}

// ---------------------------------------------------------------------------
// Skew-2 Myers step block: lane w owns word w, token t = J + i - 2w.
// Message (carry/hp31/hn31) produced by lane w-1 two wall-steps earlier ->
// shfl issues against already-final m2: SHFL is OFF the dependency chain.
// Score via final-state invariant (no per-step tracking).
// ---------------------------------------------------------------------------
template<bool GUARD>
__device__ __forceinline__ void block16_sk2(
    const unsigned* __restrict__ peqw, int w, int base_t, int n,
    unsigned C0, unsigned C1, unsigned C2, unsigned C3, unsigned Cn0,
    unsigned& VP, unsigned& VN, unsigned& Eq_a, unsigned& Eq_b,
    unsigned& m1, unsigned& m2, unsigned c_and, unsigned hp_pat)
{
    unsigned Cw[4] = {C0, C1, C2, C3};
    #pragma unroll
    for (int i = 0; i < 16; ++i) {
        const unsigned msgIn = __shfl_up_sync(0xffffffffu, m2, 1, 4);
        m2 = m1;

        const unsigned Eq = (i & 1) ? Eq_b : Eq_a;
        const int k = i + 2;                     // depth-2 PEQ prefetch
        const unsigned idn = (k < 16)
            ? __byte_perm(Cw[k >> 2], 0, 0x4440 | (k & 3))
            : __byte_perm(Cn0, 0, 0x4440 | (k & 3));
        const unsigned Eqn = peqw[(idn << 2) + w];
        if (i & 1) Eq_b = Eqn; else Eq_a = Eqn;

        const unsigned mAA  = (msgIn & c_and) | hp_pat;
        const unsigned cin  = mAA & 1u;
        const unsigned hpin = (mAA >> 1) & 1u;
        const unsigned hnin = (mAA >> 2) & 1u;

        const unsigned a = Eq & VP;
        const unsigned long long wide = (unsigned long long)a + VP + cin;
        const unsigned sum  = (unsigned)wide;
        const unsigned cout = (unsigned)(wide >> 32);
        unsigned X; LOP3_(X, sum, VP, Eq, 0xBE);     // (sum^VP)|Eq
        const unsigned D = X | VN;
        unsigned HP; LOP3_(HP, VN, D, VP, 0xF1);     // VN | ~(D|VP)
        const unsigned HN = VP & D;

        m1 = cout | (((HP >> 31) & 1u) << 1) | ((HN >> 31) << 2);

        const unsigned HPs = (HP << 1) | hpin;
        const unsigned HNs = (HN << 1) | hnin;
        unsigned nVP; LOP3_(nVP, HNs, D, HPs, 0xF1);
        const unsigned nVN = D & HPs;
        if (GUARD) {
            const bool act = ((unsigned)(base_t + i) < (unsigned)n);
            VP = act ? nVP : VP;
            VN = act ? nVN : VN;
        } else { VP = nVP; VN = nVN; }
    }
}

// window of 16 bytes starting at byte (J - 2w), built from P (J-16..) / B (J..)
__device__ __forceinline__ void win2(
    int w, uint4 P, uint4 B,
    unsigned& C0, unsigned& C1, unsigned& C2, unsigned& C3)
{
    if (w == 0)      { C0 = B.x; C1 = B.y; C2 = B.z; C3 = B.w; }
    else if (w == 1) { C0 = __funnelshift_r(P.w, B.x, 16);
                       C1 = __funnelshift_r(B.x, B.y, 16);
                       C2 = __funnelshift_r(B.y, B.z, 16);
                       C3 = __funnelshift_r(B.z, B.w, 16); }
    else if (w == 2) { C0 = P.w; C1 = B.x; C2 = B.y; C3 = B.z; }
    else             { C0 = __funnelshift_r(P.z, P.w, 16);
                       C1 = __funnelshift_r(P.w, B.x, 16);
                       C2 = __funnelshift_r(B.x, B.y, 16);
                       C3 = __funnelshift_r(B.y, B.z, 16); }
}
__device__ __forceinline__ unsigned win2_first(int w, uint4 B, uint4 Bn)
{
    if (w == 0)      return Bn.x;
    else if (w == 1) return __funnelshift_r(B.w, Bn.x, 16);
    else if (w == 2) return B.w;
    else             return __funnelshift_r(B.z, B.w, 16);
}

__device__ __forceinline__ void edit_body(
    int blk, const int* __restrict__ labels, const int* __restrict__ llen,
    char* smem_raw)
{
    unsigned* peqw = (unsigned*)smem_raw;    // 256 ids * 4 words = 4KB
    const int b = blk >> 2;
    const int pbase = (blk & 3) * 32;
    const int tid = threadIdx.x;

    for (int i = tid; i < 1024; i += 128) peqw[i] = 0u;
    __syncthreads();
    const int m = llen[b];                   // 64..128, uniform per b
    if (tid < m) {
        int c = labels[b * LL + tid];
        unsigned mp = __ldg(&g_map[(size_t)b * VV + c]);   // minpos <= tid
        atomicOr(&peqw[((mp + 1) << 2) + (tid >> 5)], 1u << (tid & 31));
    }
    __syncthreads();

    const int w = tid & 3;
    const int p_raw = pbase + (tid >> 2);
    const int p = (p_raw < PP) ? p_raw : (PP - 1);
    const int gp = b * PP + p;
    const int n = g_clen[gp];
    const unsigned char* ct = g_ctok + (size_t)gp * TT;

    int nMax = n, nMin = n;
    #pragma unroll
    for (int o = 16; o; o >>= 1) {
        nMax = max(nMax, __shfl_xor_sync(0xffffffffu, nMax, o));
        nMin = min(nMin, __shfl_xor_sync(0xffffffffu, nMin, o));
    }
    const int nWall = ((nMax + 6) + 15) & ~15;

    unsigned mask;
    if (w < 2)       mask = ~0u;
    else if (w == 2) mask = (m >= 96)  ? ~0u : ((m > 64) ? ((1u << (m - 64)) - 1u) : 0u);
    else             mask = (m >= 128) ? ~0u : ((m > 96) ? ((1u << (m - 96)) - 1u) : 0u);
    unsigned VP = mask, VN = 0u;

    const unsigned c_and  = w ? 7u : 0u;
    const unsigned hp_pat = w ? 0u : 2u;     // lane0: hpin=1 (D[j][0]=j boundary)
    unsigned m1 = 0u, m2 = 0u;

    uint4 P  = make_uint4(0, 0, 0, 0);
    uint4 B  = *(const uint4*)(ct);
    uint4 Bn = *(const uint4*)(ct + 16);
    unsigned C0, C1, C2, C3;
    win2(w, P, B, C0, C1, C2, C3);
    unsigned Eq_a = peqw[(__byte_perm(C0, 0, 0x4440) << 2) + w];
    unsigned Eq_b = peqw[(__byte_perm(C0, 0, 0x4441) << 2) + w];

    for (int J = 0; J < nWall; J += 16) {
        const uint4 Bf = *(const uint4*)(ct + J + 32);   // within +128 pad
        const unsigned Cn0 = win2_first(w, B, Bn);
        const int base_t = J - 2 * w;
        if (J == 0 || (J + 15) >= nMin)
            block16_sk2<true >(peqw, w, base_t, n, C0, C1, C2, C3, Cn0,
                               VP, VN, Eq_a, Eq_b, m1, m2, c_and, hp_pat);
        else
            block16_sk2<false>(peqw, w, base_t, n, C0, C1, C2, C3, Cn0,
                               VP, VN, Eq_a, Eq_b, m1, m2, c_and, hp_pat);
        P = B; B = Bn; Bn = Bf;
        win2(w, P, B, C0, C1, C2, C3);
    }

    // D[n][m] = n + popc(VP&mask) - popc(VN&mask) summed over the 4 words
    int partial = __popc(VP & mask) - __popc(VN & mask);
    partial += __shfl_xor_sync(0xffffffffu, partial, 1, 4);
    partial += __shfl_xor_sync(0xffffffffu, partial, 2, 4);
    if ((tid & 3) == 0 && p_raw < PP)
        g_wers[b * PP + p_raw] = (float)(n + partial);
    __syncthreads();
}

// ---------------------------------------------------------------------------
// Scores: log-softmax normalizer cancels in the per-b softmax over paths.
// Fat blocks: each handles 8 consecutive bp (keeps the warp census low so
// edit blocks get issue slots from t=0).
// ---------------------------------------------------------------------------
__device__ __forceinline__ void scores_multi(
    int blk, const float* __restrict__ em, const int* __restrict__ elen,
    const int* __restrict__ paths, char* smem_raw)
{
    const int tid = threadIdx.x;
    const int t0 = tid * 8;
    float* ws = (float*)smem_raw;

    #pragma unroll 1
    for (int q = 0; q < 8; ++q) {
        const int bp  = blk * 8 + q;
        const int b   = bp / PP;
        const int len = elen[b];
        const int* pp = paths + (size_t)bp * TT;
        const float* eb = em + (size_t)b * TT * VV;

        int4 A = *(const int4*)(pp + t0);
        int4 Bv = *(const int4*)(pp + t0 + 4);
        int tok[8] = {A.x, A.y, A.z, A.w, Bv.x, Bv.y, Bv.z, Bv.w};

        float a0 = 0.f, a1 = 0.f, a2 = 0.f, a3 = 0.f;
        #pragma unroll
        for (int i = 0; i < 8; i += 4) {
            if (t0 + i + 0 < len) a0 += __ldg(eb + (size_t)(t0 + i + 0) * VV + tok[i + 0]);
            if (t0 + i + 1 < len) a1 += __ldg(eb + (size_t)(t0 + i + 1) * VV + tok[i + 1]);
            if (t0 + i + 2 < len) a2 += __ldg(eb + (size_t)(t0 + i + 2) * VV + tok[i + 2]);
            if (t0 + i + 3 < len) a3 += __ldg(eb + (size_t)(t0 + i + 3) * VV + tok[i + 3]);
        }
        float acc = (a0 + a1) + (a2 + a3);
        #pragma unroll
        for (int o = 16; o; o >>= 1) acc += __shfl_down_sync(0xffffffffu, acc, o);
        if ((tid & 31) == 0) ws[tid >> 5] = acc;
        __syncthreads();
        if (tid == 0) g_scores[bp] = ws[0] + ws[1] + ws[2] + ws[3];
        __syncthreads();
    }
}

__device__ __forceinline__ void finalize_body(float* out, char* smem_raw)
{
    float* red = (float*)smem_raw;
    const int tid = threadIdx.x;
    float total = 0.f;
    __threadfence();

    for (int b = 0; b < BB; ++b) {
        float s = (tid < PP) ? g_scores[b * PP + tid] : -3.0e38f;
        red[tid] = s; __syncthreads();
        #pragma unroll
        for (int o = 64; o; o >>= 1) {
            if (tid < o) red[tid] = fmaxf(red[tid], red[tid + o]);
            __syncthreads();
        }
        const float mx = red[0];
        __syncthreads();

        const float e  = (tid < PP) ? expf(s - mx) : 0.f;
        const float ew = (tid < PP) ? e * g_wers[b * PP + tid] : 0.f;

        red[tid] = e; __syncthreads();
        #pragma unroll
        for (int o = 64; o; o >>= 1) {
            if (tid < o) red[tid] += red[tid + o];
            __syncthreads();
        }
        const float Z = red[0];
        __syncthreads();

        red[tid] = ew; __syncthreads();
        #pragma unroll
        for (int o = 64; o; o >>= 1) {
            if (tid < o) red[tid] += red[tid + o];
            __syncthreads();
        }
        const float S = red[0];
        __syncthreads();

        total += S / Z;
    }
    if (tid == 0) out[0] = total;
}

__global__ void __launch_bounds__(128) fused_kernel(
    const float* __restrict__ em,
    const int* __restrict__ elen,
    const int* __restrict__ paths,
    const int* __restrict__ labels,
    const int* __restrict__ llen,
    float* __restrict__ out)
{
    extern __shared__ char smem_raw[];
    __shared__ unsigned s_rank;

    if (blockIdx.x < NEDIT)
        edit_body(blockIdx.x, labels, llen, smem_raw);
    else
        scores_multi(blockIdx.x - NEDIT, em, elen, paths, smem_raw);

    if (threadIdx.x == 0) {
        __threadfence();
        s_rank = atomicAdd(&g_done, 1u);
    }
    __syncthreads();
    if (s_rank == (unsigned)(NEDIT + NSCORE - 1))
        finalize_body(out, smem_raw);
}

// ---------------------------------------------------------------------------
extern "C" void kernel_launch(void* const* d_in, const int* in_sizes, int n_in,
                              void* d_out, int out_size)
{
    const float* em     = (const float*)d_in[0];  // (B,T,V) f32
    const int*   elen   = (const int*)  d_in[1];  // (B,)
    const int*   labels = (const int*)  d_in[2];  // (B,L)
    const int*   llen   = (const int*)  d_in[3];  // (B,)
    const int*   paths  = (const int*)  d_in[4];  // (B,P,T)

    clear_kernel<<<256, 128>>>();
    scatter_kernel<<<BB, 128>>>(labels, llen);
    compact_kernel<<<BB * PP, 128>>>(paths, elen);

    const int smem = 4096 + 512;   // peq (4KB) + reduction scratch
    fused_kernel<<<NEDIT + NSCORE, 128, smem>>>(em, elen, paths, labels, llen,
                                                (float*)d_out);
}